// round 1
// baseline (speedup 1.0000x reference)
#include <cuda_runtime.h>

// Problem dims (fixed by the reference)
#define B_ROWS 32768
#define D_IN   200
#define H_DIM  100
#define K_SAMP 10

// Scratch (device globals — no allocation allowed)
__device__ float g_h1[B_ROWS * H_DIM];
__device__ float g_h2[B_ROWS * H_DIM];
__device__ float g_logits[B_ROWS * D_IN];

// ---------------- packed f32x2 helpers (Blackwell) ----------------
__device__ __forceinline__ unsigned long long pack2(float lo, float hi) {
    unsigned long long r;
    asm("mov.b64 %0, {%1, %2};" : "=l"(r) : "f"(lo), "f"(hi));
    return r;
}
__device__ __forceinline__ void unpack2(unsigned long long v, float& lo, float& hi) {
    asm("mov.b64 {%0, %1}, %2;" : "=f"(lo), "=f"(hi) : "l"(v));
}
__device__ __forceinline__ unsigned long long fma2(unsigned long long a,
                                                   unsigned long long b,
                                                   unsigned long long c) {
    unsigned long long d;
    asm("fma.rn.f32x2 %0, %1, %2, %3;" : "=l"(d) : "l"(a), "l"(b), "l"(c));
    return d;
}

// ---------------- tiled GEMM: C[M,N] = act(A[M,KD] @ W[KD,N] + bias) ----------------
// TM=64 rows per CTA, 256 threads. BK=25 divides both 100 and 200.
// Thread (tx,ty): tx = lane (col strips col = tx + 32*c), ty = warp (8 rows, as 4 row-pairs).
template <int N, int KD, bool RELU>
__global__ __launch_bounds__(256) void gemm_kernel(const float* __restrict__ A,
                                                   const float* __restrict__ W,
                                                   const float* __restrict__ bias,
                                                   float* __restrict__ C) {
    constexpr int TM = 64;
    constexpr int BK = 25;
    constexpr int CI = (N + 31) / 32;

    __shared__ float Xs[TM][BK];
    __shared__ float Ws[BK][N];

    const int tid = threadIdx.x;
    const int tx = tid & 31;
    const int ty = tid >> 5;  // 0..7
    const int rowBase = blockIdx.x * TM;

    unsigned long long acc[4][CI];
#pragma unroll
    for (int r = 0; r < 4; r++)
#pragma unroll
        for (int c = 0; c < CI; c++) acc[r][c] = 0ull;

    for (int k0 = 0; k0 < KD; k0 += BK) {
        // stage A tile
        for (int idx = tid; idx < TM * BK; idx += 256) {
            int r = idx / BK;
            int kk = idx - r * BK;
            Xs[r][kk] = A[(size_t)(rowBase + r) * KD + k0 + kk];
        }
        // stage W tile
        for (int idx = tid; idx < BK * N; idx += 256) {
            int kk = idx / N;
            int c = idx - kk * N;
            Ws[kk][c] = W[(size_t)(k0 + kk) * N + c];
        }
        __syncthreads();

#pragma unroll 5
        for (int kk = 0; kk < BK; kk++) {
            unsigned long long ap[4];
#pragma unroll
            for (int r = 0; r < 4; r++)
                ap[r] = pack2(Xs[ty * 8 + 2 * r][kk], Xs[ty * 8 + 2 * r + 1][kk]);
            unsigned long long wp[CI];
#pragma unroll
            for (int c = 0; c < CI; c++) {
                int col = tx + 32 * c;
                float wv = (col < N) ? Ws[kk][col] : 0.0f;
                wp[c] = pack2(wv, wv);
            }
#pragma unroll
            for (int r = 0; r < 4; r++)
#pragma unroll
                for (int c = 0; c < CI; c++) acc[r][c] = fma2(ap[r], wp[c], acc[r][c]);
        }
        __syncthreads();
    }

    // epilogue: bias (+relu), write two rows per pair
#pragma unroll
    for (int r = 0; r < 4; r++) {
        int row0 = rowBase + ty * 8 + 2 * r;
#pragma unroll
        for (int c = 0; c < CI; c++) {
            int col = tx + 32 * c;
            if (col < N) {
                float lo, hi;
                unpack2(acc[r][c], lo, hi);
                float bv = bias[col];
                lo += bv;
                hi += bv;
                if (RELU) {
                    lo = fmaxf(lo, 0.0f);
                    hi = fmaxf(hi, 0.0f);
                }
                C[(size_t)row0 * N + col] = lo;
                C[(size_t)(row0 + 1) * N + col] = hi;
            }
        }
    }
}

// ---------------- sampling + output head: one warp per row ----------------
// samples[b,d] = max_k softmax_d( 2*( -log(-log(clip(u))) + logits[b,d] ) )
// preds[b,:]   = softmax( (x[b,:]*samples[b,:]) @ wo + bo )
__global__ __launch_bounds__(256) void sample_kernel(const float* __restrict__ x,
                                                     const float* __restrict__ uniform,
                                                     const float* __restrict__ logits,
                                                     const float* __restrict__ wo,
                                                     const float* __restrict__ bo,
                                                     float* __restrict__ out) {
    const int gwarp = (blockIdx.x * blockDim.x + threadIdx.x) >> 5;
    const int lane = threadIdx.x & 31;
    if (gwarp >= B_ROWS) return;
    const int b = gwarp;

    constexpr int NE = 7;  // ceil(200/32)
    constexpr float EPSF = 1.1920929e-07f;

    float lg[NE], xv[NE], smp[NE];
#pragma unroll
    for (int i = 0; i < NE; i++) {
        int d = lane + 32 * i;
        bool ok = d < D_IN;
        lg[i] = ok ? logits[(size_t)b * D_IN + d] : 0.0f;
        xv[i] = ok ? x[(size_t)b * D_IN + d] : 0.0f;
        smp[i] = 0.0f;
    }

    const float* up = uniform + (size_t)b * K_SAMP * D_IN;

    for (int k = 0; k < K_SAMP; k++) {
        float v[NE];
        float m = -1e30f;
#pragma unroll
        for (int i = 0; i < NE; i++) {
            int d = lane + 32 * i;
            float u = (d < D_IN) ? up[k * D_IN + d] : 0.5f;
            u = fminf(fmaxf(u, EPSF), 1.0f);
            float t;
            if (u > 0.99f) {
                // accurate -log(u) = -log1p(u-1) ~ -(x - x^2/2 + x^3/3), |x|<=0.01
                float xm = u - 1.0f;
                t = -(xm - 0.5f * xm * xm + 0.33333333f * xm * xm * xm);
            } else {
                t = -__logf(u);
            }
            float g = -__logf(t);
            float vv = 2.0f * (g + lg[i]);  // / tau0 (0.5)
            v[i] = (d < D_IN) ? vv : -1e30f;
            m = fmaxf(m, v[i]);
        }
#pragma unroll
        for (int off = 16; off > 0; off >>= 1)
            m = fmaxf(m, __shfl_xor_sync(0xffffffffu, m, off));

        float e[NE];
        float s = 0.0f;
#pragma unroll
        for (int i = 0; i < NE; i++) {
            int d = lane + 32 * i;
            e[i] = (d < D_IN) ? __expf(v[i] - m) : 0.0f;
            s += e[i];
        }
#pragma unroll
        for (int off = 16; off > 0; off >>= 1)
            s += __shfl_xor_sync(0xffffffffu, s, off);

        float inv = 1.0f / s;
#pragma unroll
        for (int i = 0; i < NE; i++) smp[i] = fmaxf(smp[i], e[i] * inv);
    }

    // write samples (offset B*2: preds first, then samples)
    float* samples_out = out + (size_t)B_ROWS * 2;
#pragma unroll
    for (int i = 0; i < NE; i++) {
        int d = lane + 32 * i;
        if (d < D_IN) samples_out[(size_t)b * D_IN + d] = smp[i];
    }

    // preds head: xs @ wo + bo, softmax over 2 classes
    float p0 = 0.0f, p1 = 0.0f;
#pragma unroll
    for (int i = 0; i < NE; i++) {
        int d = lane + 32 * i;
        if (d < D_IN) {
            float xs = xv[i] * smp[i];
            p0 += xs * wo[d * 2 + 0];
            p1 += xs * wo[d * 2 + 1];
        }
    }
#pragma unroll
    for (int off = 16; off > 0; off >>= 1) {
        p0 += __shfl_xor_sync(0xffffffffu, p0, off);
        p1 += __shfl_xor_sync(0xffffffffu, p1, off);
    }
    if (lane == 0) {
        p0 += bo[0];
        p1 += bo[1];
        float mm = fmaxf(p0, p1);
        float e0 = __expf(p0 - mm);
        float e1 = __expf(p1 - mm);
        float is = 1.0f / (e0 + e1);
        out[(size_t)b * 2 + 0] = e0 * is;
        out[(size_t)b * 2 + 1] = e1 * is;
    }
}

extern "C" void kernel_launch(void* const* d_in, const int* in_sizes, int n_in,
                              void* d_out, int out_size) {
    const float* x  = (const float*)d_in[0];
    const float* un = (const float*)d_in[1];
    const float* w1 = (const float*)d_in[2];
    const float* b1 = (const float*)d_in[3];
    const float* w2 = (const float*)d_in[4];
    const float* b2 = (const float*)d_in[5];
    const float* wl = (const float*)d_in[6];
    const float* bl = (const float*)d_in[7];
    const float* wo = (const float*)d_in[8];
    const float* bo = (const float*)d_in[9];
    float* out = (float*)d_out;

    float *h1, *h2, *lgts;
    cudaGetSymbolAddress((void**)&h1, g_h1);
    cudaGetSymbolAddress((void**)&h2, g_h2);
    cudaGetSymbolAddress((void**)&lgts, g_logits);

    const int gemm_blocks = B_ROWS / 64;  // 512

    gemm_kernel<H_DIM, D_IN, true><<<gemm_blocks, 256>>>(x, w1, b1, h1);
    gemm_kernel<H_DIM, H_DIM, true><<<gemm_blocks, 256>>>(h1, w2, b2, h2);
    gemm_kernel<D_IN, H_DIM, false><<<gemm_blocks, 256>>>(h2, wl, bl, lgts);

    // one warp per row: 32768 warps = 4096 blocks of 8 warps
    sample_kernel<<<B_ROWS / 8, 256>>>(x, un, lgts, wo, bo, out);
}

// round 2
// speedup vs baseline: 1.1668x; 1.1668x over previous
#include <cuda_runtime.h>

#define B_ROWS 32768
#define D_IN   200
#define H_DIM  100
#define K_SAMP 10

// scratch: logits only (h1/h2 now live in SMEM)
__device__ float g_logits[(size_t)B_ROWS * D_IN];

typedef unsigned long long ull;

__device__ __forceinline__ ull dup2(float w) {
    ull r; asm("mov.b64 %0, {%1, %1};" : "=l"(r) : "f"(w)); return r;
}
__device__ __forceinline__ ull fma2(ull a, ull b, ull c) {
    ull d; asm("fma.rn.f32x2 %0, %1, %2, %3;" : "=l"(d) : "l"(a), "l"(b), "l"(c)); return d;
}
__device__ __forceinline__ void unpack2(ull v, float& lo, float& hi) {
    asm("mov.b64 {%0, %1}, %2;" : "=f"(lo), "=f"(hi) : "l"(v));
}
__device__ __forceinline__ float frcp(float x) {
    float r; asm("rcp.approx.f32 %0, %1;" : "=f"(r) : "f"(x)); return r;
}

// ---------------- fused MLP: x -> relu -> relu -> logits ----------------
// CTA = 64 rows, 256 threads (8 warps * 8 rows). SMEM layout (floats):
//   XsT[200][68]  transposed x (k-major, row minor)  — reused as H2T after layer1
//   H1T[100][68]
//   WS [224*20]   per-chunk weight tile, transposed WsT[col][kk], BK=20
#define APAD 68
#define BK   20
#define WSN  224
#define OFF_XST 0
#define OFF_H1T (200 * APAD)
#define OFF_WS  (200 * APAD + 100 * APAD)
#define SMEM_FLOATS (200 * APAD + 100 * APAD + WSN * BK)

template <int K, int N, int CI, bool RELU, bool TOSMEM>
__device__ __forceinline__ void layer_gemm(float* smem,
                                           const float* Asm,   // smem [K][APAD]
                                           const float* __restrict__ Wg,  // [K][N]
                                           const float* __restrict__ bg,  // [N]
                                           float* Hsm,          // smem out [N][APAD]
                                           float* __restrict__ Gout,  // global out
                                           int rowBase, int tid) {
    float* ws = smem + OFF_WS;
    const int lane = tid & 31;
    const int wy = tid >> 5;  // rows [8wy, 8wy+8)

    ull acc[4][CI];
#pragma unroll
    for (int r = 0; r < 4; r++)
#pragma unroll
        for (int c = 0; c < CI; c++) acc[r][c] = 0ull;

    for (int k0 = 0; k0 < K; k0 += BK) {
        __syncthreads();
        // stage weight chunk transposed: ws[col*BK + kk] = W[k0+kk][col]
        for (int it = tid; it < BK * N; it += 256) {
            int kk = it / N;
            int c = it - kk * N;
            ws[c * BK + kk] = Wg[(size_t)(k0 + kk) * N + c];
        }
        __syncthreads();

        const float* abase = Asm + k0 * APAD + wy * 8;
#pragma unroll
        for (int kk = 0; kk < BK; kk += 4) {
            float4 wv[CI];
#pragma unroll
            for (int c = 0; c < CI; c++) {
                int col = lane + 32 * c;  // may exceed N; ws is padded, values unused
                wv[c] = *(const float4*)&ws[col * BK + kk];
            }
#pragma unroll
            for (int j = 0; j < 4; j++) {
                const float* arow = abase + (kk + j) * APAD;
                ulonglong2 a01 = *(const ulonglong2*)(arow);
                ulonglong2 a23 = *(const ulonglong2*)(arow + 4);
                ull ap0 = a01.x, ap1 = a01.y, ap2 = a23.x, ap3 = a23.y;
#pragma unroll
                for (int c = 0; c < CI; c++) {
                    float wj = (j == 0) ? wv[c].x : (j == 1) ? wv[c].y : (j == 2) ? wv[c].z : wv[c].w;
                    ull wp = dup2(wj);
                    acc[0][c] = fma2(ap0, wp, acc[0][c]);
                    acc[1][c] = fma2(ap1, wp, acc[1][c]);
                    acc[2][c] = fma2(ap2, wp, acc[2][c]);
                    acc[3][c] = fma2(ap3, wp, acc[3][c]);
                }
            }
        }
    }

    // epilogue
#pragma unroll
    for (int c = 0; c < CI; c++) {
        int col = lane + 32 * c;
        if (col < N) {
            float bv = __ldg(&bg[col]);
#pragma unroll
            for (int r = 0; r < 4; r++) {
                float lo, hi;
                unpack2(acc[r][c], lo, hi);
                lo += bv; hi += bv;
                if (RELU) { lo = fmaxf(lo, 0.0f); hi = fmaxf(hi, 0.0f); }
                int row = wy * 8 + 2 * r;
                if (TOSMEM) {
                    *(float2*)&Hsm[col * APAD + row] = make_float2(lo, hi);
                } else {
                    Gout[(size_t)(rowBase + row) * N + col] = lo;
                    Gout[(size_t)(rowBase + row + 1) * N + col] = hi;
                }
            }
        }
    }
}

__global__ __launch_bounds__(256, 2) void mlp_kernel(const float* __restrict__ x,
                                                     const float* __restrict__ w1,
                                                     const float* __restrict__ b1,
                                                     const float* __restrict__ w2,
                                                     const float* __restrict__ b2,
                                                     const float* __restrict__ wl,
                                                     const float* __restrict__ bl,
                                                     float* __restrict__ logits) {
    extern __shared__ float smem[];
    const int tid = threadIdx.x;
    const int rowBase = blockIdx.x * 64;

    // stage x block transposed: XsT[k][row]
    {
        const float4* xb = (const float4*)(x + (size_t)rowBase * D_IN);
        for (int it = tid; it < 64 * 50; it += 256) {
            int q = it >> 6;       // 0..49 (k quad)
            int row = it & 63;     // conflict-free STS (consecutive lanes -> consecutive rows)
            float4 v = xb[row * 50 + q];
            float* p = smem + OFF_XST + (4 * q) * APAD + row;
            p[0 * APAD] = v.x;
            p[1 * APAD] = v.y;
            p[2 * APAD] = v.z;
            p[3 * APAD] = v.w;
        }
    }
    // layer1: (200 -> 100) relu, out H1T
    layer_gemm<200, 100, 4, true, true>(smem, smem + OFF_XST, w1, b1, smem + OFF_H1T,
                                        nullptr, rowBase, tid);
    // layer2: (100 -> 100) relu, out H2T overlaid on XsT (x dead)
    layer_gemm<100, 100, 4, true, true>(smem, smem + OFF_H1T, w2, b2, smem + OFF_XST,
                                        nullptr, rowBase, tid);
    // layer3: (100 -> 200) linear, out -> global logits
    layer_gemm<100, 200, 7, false, false>(smem, smem + OFF_XST, wl, bl, nullptr,
                                          logits, rowBase, tid);
}

// ---------------- sampling + output head: one warp per row ----------------
// softmax_d(2(g+lg)) with g=-log t, t=-log u  ==  (E_d / t^2) / sum,  E_d = exp(2(lg_d - max lg))
__global__ __launch_bounds__(256) void sample_kernel(const float* __restrict__ x,
                                                     const float* __restrict__ uniform,
                                                     const float* __restrict__ logits,
                                                     const float* __restrict__ wo,
                                                     const float* __restrict__ bo,
                                                     float* __restrict__ out) {
    const int b = (blockIdx.x * blockDim.x + threadIdx.x) >> 5;
    const int lane = threadIdx.x & 31;
    if (b >= B_ROWS) return;

    constexpr int NE = 7;
    constexpr float EPSF = 1.1920929e-07f;

    float E[NE], xv[NE], smp[NE];
    float mlg = -1e30f;
#pragma unroll
    for (int i = 0; i < NE; i++) {
        int d = lane + 32 * i;
        bool ok = d < D_IN;
        float lg = ok ? logits[(size_t)b * D_IN + d] : -1e30f;
        E[i] = lg;  // stash, finish after max
        xv[i] = ok ? x[(size_t)b * D_IN + d] : 0.0f;
        smp[i] = 0.0f;
        mlg = fmaxf(mlg, lg);
    }
#pragma unroll
    for (int off = 16; off > 0; off >>= 1)
        mlg = fmaxf(mlg, __shfl_xor_sync(0xffffffffu, mlg, off));
#pragma unroll
    for (int i = 0; i < NE; i++) {
        int d = lane + 32 * i;
        E[i] = (d < D_IN) ? __expf(2.0f * (E[i] - mlg)) : 0.0f;  // E=0 kills padding lanes
    }

    const float* up = uniform + (size_t)b * K_SAMP * D_IN;

    for (int k = 0; k < K_SAMP; k++) {
        float w[NE];
        float s = 0.0f;
#pragma unroll
        for (int i = 0; i < NE; i++) {
            int d = lane + 32 * i;
            float u = (d < D_IN) ? up[k * D_IN + d] : 0.5f;
            u = fmaxf(u, EPSF);            // u < 1 guaranteed by uniform
            float tl = -__logf(u);         // fast path
            float xm = u - 1.0f;           // exact for u near 1
            // -log1p(xm) = xm*(xm*(-xm/3 + 1/2) - 1)
            float tp = xm * fmaf(xm, fmaf(xm, -0.33333333f, 0.5f), -1.0f);
            float t = (u > 0.99f) ? tp : tl;
            float r = frcp(t);
            float wi = E[i] * r * r;       // = exp(2(lg-mlg)) / t^2
            w[i] = wi;
            s += wi;
        }
#pragma unroll
        for (int off = 16; off > 0; off >>= 1)
            s += __shfl_xor_sync(0xffffffffu, s, off);
        float inv = frcp(s);
#pragma unroll
        for (int i = 0; i < NE; i++) smp[i] = fmaxf(smp[i], w[i] * inv);
    }

    // samples out (preds occupy first B*2)
    float* samples_out = out + (size_t)B_ROWS * 2;
#pragma unroll
    for (int i = 0; i < NE; i++) {
        int d = lane + 32 * i;
        if (d < D_IN) samples_out[(size_t)b * D_IN + d] = smp[i];
    }

    // preds head
    float p0 = 0.0f, p1 = 0.0f;
#pragma unroll
    for (int i = 0; i < NE; i++) {
        int d = lane + 32 * i;
        if (d < D_IN) {
            float xs = xv[i] * smp[i];
            p0 += xs * wo[d * 2 + 0];
            p1 += xs * wo[d * 2 + 1];
        }
    }
#pragma unroll
    for (int off = 16; off > 0; off >>= 1) {
        p0 += __shfl_xor_sync(0xffffffffu, p0, off);
        p1 += __shfl_xor_sync(0xffffffffu, p1, off);
    }
    if (lane == 0) {
        p0 += bo[0];
        p1 += bo[1];
        float mm = fmaxf(p0, p1);
        float e0 = __expf(p0 - mm);
        float e1 = __expf(p1 - mm);
        float is = 1.0f / (e0 + e1);
        out[(size_t)b * 2 + 0] = e0 * is;
        out[(size_t)b * 2 + 1] = e1 * is;
    }
}

extern "C" void kernel_launch(void* const* d_in, const int* in_sizes, int n_in,
                              void* d_out, int out_size) {
    const float* x  = (const float*)d_in[0];
    const float* un = (const float*)d_in[1];
    const float* w1 = (const float*)d_in[2];
    const float* b1 = (const float*)d_in[3];
    const float* w2 = (const float*)d_in[4];
    const float* b2 = (const float*)d_in[5];
    const float* wl = (const float*)d_in[6];
    const float* bl = (const float*)d_in[7];
    const float* wo = (const float*)d_in[8];
    const float* bo = (const float*)d_in[9];
    float* out = (float*)d_out;

    float* lgts;
    cudaGetSymbolAddress((void**)&lgts, g_logits);

    const int smem_bytes = SMEM_FLOATS * (int)sizeof(float);  // 99520
    cudaFuncSetAttribute(mlp_kernel, cudaFuncAttributeMaxDynamicSharedMemorySize, smem_bytes);

    mlp_kernel<<<B_ROWS / 64, 256, smem_bytes>>>(x, w1, b1, w2, b2, wl, bl, lgts);
    sample_kernel<<<B_ROWS / 8, 256>>>(x, un, lgts, wo, bo, out);
}

// round 3
// speedup vs baseline: 1.2338x; 1.0574x over previous
#include <cuda_runtime.h>

#define B_ROWS 32768
#define D_IN   200
#define K_SAMP 10
#define TM     64
#define APAD   64

// smem layout (floats)
#define OFF_R0 0                      // XsT[200][64] -> later Lg[64][200] row-major
#define OFF_R1 (200 * APAD)           // H1T[100][64]
#define OFF_R2 (OFF_R1 + 100 * APAD)  // H2T[100][64]
#define OFF_WS (OFF_R2 + 100 * APAD)  // weight chunk: max(128*20, 224*10) = 2560
#define WS_FLOATS 2560
#define SMEM_FLOATS (OFF_WS + WS_FLOATS)

typedef unsigned long long ull;

__device__ __forceinline__ ull dup2(float w) {
    ull r; asm("mov.b64 %0, {%1, %1};" : "=l"(r) : "f"(w)); return r;
}
__device__ __forceinline__ ull fma2(ull a, ull b, ull c) {
    ull d; asm("fma.rn.f32x2 %0, %1, %2, %3;" : "=l"(d) : "l"(a), "l"(b), "l"(c)); return d;
}
__device__ __forceinline__ void unpack2(ull v, float& lo, float& hi) {
    asm("mov.b64 {%0, %1}, %2;" : "=f"(lo), "=f"(hi) : "l"(v));
}
__device__ __forceinline__ float frcp(float x) {
    float r; asm("rcp.approx.f32 %0, %1;" : "=f"(r) : "f"(x)); return r;
}

// one GEMM layer over the CTA's 64 rows; A in smem [K][APAD] (k-major), W global [K][N]
template <int K, int N, int CI, int BK, bool RELU, bool ROWMAJOR>
__device__ __forceinline__ void layer(float* smem, const float* Asm,
                                      const float* __restrict__ Wg,
                                      const float* __restrict__ bg,
                                      float* Hout, int tid) {
    constexpr int KSTEP = (BK % 4 == 0) ? 4 : 2;
    constexpr int NLD = (BK * N + 255) / 256;
    float* ws = smem + OFF_WS;
    const int lane = tid & 31;
    const int wy = tid >> 5;

    ull acc[4][CI];
#pragma unroll
    for (int r = 0; r < 4; r++)
#pragma unroll
        for (int c = 0; c < CI; c++) acc[r][c] = 0ull;

    float pf[NLD];
    // prefetch chunk 0 into regs
#pragma unroll
    for (int i = 0; i < NLD; i++) {
        int idx = tid + 256 * i;
        if (idx < BK * N) pf[i] = Wg[idx];
    }
    __syncthreads();  // prior users of WS / writers of Asm done
#pragma unroll
    for (int i = 0; i < NLD; i++) {
        int idx = tid + 256 * i;
        if (idx < BK * N) { int kk = idx / N, c = idx - kk * N; ws[c * BK + kk] = pf[i]; }
    }
    __syncthreads();

    for (int k0 = 0; k0 < K; k0 += BK) {
        const bool more = (k0 + BK) < K;
        if (more) {
            const float* wnext = Wg + (size_t)(k0 + BK) * N;
#pragma unroll
            for (int i = 0; i < NLD; i++) {
                int idx = tid + 256 * i;
                if (idx < BK * N) pf[i] = wnext[idx];
            }
        }
        const float* abase = Asm + k0 * APAD + wy * 8;
#pragma unroll
        for (int kk = 0; kk < BK; kk += KSTEP) {
            float wv[CI][KSTEP];
#pragma unroll
            for (int c = 0; c < CI; c++) {
                const float* wp_ = &ws[(lane + 32 * c) * BK + kk];
                if (KSTEP == 4) {
                    float4 v = *(const float4*)wp_;
                    wv[c][0] = v.x; wv[c][1] = v.y; wv[c][2] = v.z; wv[c][3] = v.w;
                } else {
                    float2 v = *(const float2*)wp_;
                    wv[c][0] = v.x; wv[c][1] = v.y;
                }
            }
#pragma unroll
            for (int j = 0; j < KSTEP; j++) {
                const float* arow = abase + (kk + j) * APAD;
                ulonglong2 a01 = *(const ulonglong2*)arow;
                ulonglong2 a23 = *(const ulonglong2*)(arow + 4);
#pragma unroll
                for (int c = 0; c < CI; c++) {
                    ull wp = dup2(wv[c][j]);
                    acc[0][c] = fma2(a01.x, wp, acc[0][c]);
                    acc[1][c] = fma2(a01.y, wp, acc[1][c]);
                    acc[2][c] = fma2(a23.x, wp, acc[2][c]);
                    acc[3][c] = fma2(a23.y, wp, acc[3][c]);
                }
            }
        }
        if (more) {
            __syncthreads();
#pragma unroll
            for (int i = 0; i < NLD; i++) {
                int idx = tid + 256 * i;
                if (idx < BK * N) { int kk = idx / N, c = idx - kk * N; ws[c * BK + kk] = pf[i]; }
            }
            __syncthreads();
        }
    }

    // epilogue
#pragma unroll
    for (int c = 0; c < CI; c++) {
        int col = lane + 32 * c;
        if (col < N) {
            float bv = bg[col];
#pragma unroll
            for (int r = 0; r < 4; r++) {
                float lo, hi;
                unpack2(acc[r][c], lo, hi);
                lo += bv; hi += bv;
                if (RELU) { lo = fmaxf(lo, 0.0f); hi = fmaxf(hi, 0.0f); }
                int row = wy * 8 + 2 * r;
                if (ROWMAJOR) {
                    Hout[row * N + col] = lo;
                    Hout[(row + 1) * N + col] = hi;
                } else {
                    *(float2*)&Hout[col * APAD + row] = make_float2(lo, hi);
                }
            }
        }
    }
}

__global__ __launch_bounds__(256, 2) void fused_kernel(
    const float* __restrict__ x, const float* __restrict__ uniform,
    const float* __restrict__ w1, const float* __restrict__ b1,
    const float* __restrict__ w2, const float* __restrict__ b2,
    const float* __restrict__ wl, const float* __restrict__ bl,
    const float* __restrict__ wo, const float* __restrict__ bo,
    float* __restrict__ out) {
    extern __shared__ float smem[];
    const int tid = threadIdx.x;
    const int lane = tid & 31;
    const int wy = tid >> 5;
    const int rowBase = blockIdx.x * TM;

    // stage x transposed: XsT[k][row]; LDG strided (L1-absorbed), STS conflict-free
    {
        const float4* xb = (const float4*)(x + (size_t)rowBase * D_IN);
        for (int it = tid; it < 64 * 50; it += 256) {
            int q = it >> 6, row = it & 63;
            float4 v = xb[row * 50 + q];
            float* p = smem + OFF_R0 + (4 * q) * APAD + row;
            p[0] = v.x; p[APAD] = v.y; p[2 * APAD] = v.z; p[3 * APAD] = v.w;
        }
    }
    layer<200, 100, 4, 20, true, false>(smem, smem + OFF_R0, w1, b1, smem + OFF_R1, tid);
    layer<100, 100, 4, 20, true, false>(smem, smem + OFF_R1, w2, b2, smem + OFF_R2, tid);
    layer<100, 200, 7, 10, false, true>(smem, smem + OFF_R2, wl, bl, smem + OFF_R0, tid);
    // each warp's logits rows are its own -> no barrier; warps flow into sampling staggered

    const float* Lg = smem + OFF_R0;
    float* samples_out = out + (size_t)B_ROWS * 2;
    constexpr float EPSF = 1.1920929e-07f;
    const bool v3 = lane < 4;  // tail quad d=192+2*lane valid only for lane<4

    for (int p = 0; p < 4; p++) {
        const int r0 = wy * 8 + 2 * p;
        const int gb0 = rowBase + r0, gb1 = gb0 + 1;

        // logits for both rows (8 scalars each: d = 2*lane + 64*i + comp)
        float la[8], lb[8];
#pragma unroll
        for (int i = 0; i < 4; i++) {
            float2 a = *(const float2*)&Lg[r0 * 200 + 2 * lane + 64 * i];
            float2 b = *(const float2*)&Lg[(r0 + 1) * 200 + 2 * lane + 64 * i];
            la[2 * i] = a.x; la[2 * i + 1] = a.y;
            lb[2 * i] = b.x; lb[2 * i + 1] = b.y;
        }
        float mA = -1e30f, mB = -1e30f;
#pragma unroll
        for (int i = 0; i < 8; i++) {
            bool ok = (i < 6) || v3;
            if (!ok) { la[i] = -1e30f; lb[i] = -1e30f; }
            mA = fmaxf(mA, la[i]);
            mB = fmaxf(mB, lb[i]);
        }
#pragma unroll
        for (int off = 16; off > 0; off >>= 1) {
            mA = fmaxf(mA, __shfl_xor_sync(0xffffffffu, mA, off));
            mB = fmaxf(mB, __shfl_xor_sync(0xffffffffu, mB, off));
        }
        float EA[8], EB[8], sa[8], sb[8];
#pragma unroll
        for (int i = 0; i < 8; i++) {
            bool ok = (i < 6) || v3;
            EA[i] = ok ? __expf(2.0f * (la[i] - mA)) : 0.0f;
            EB[i] = ok ? __expf(2.0f * (lb[i] - mB)) : 0.0f;
            sa[i] = 0.0f; sb[i] = 0.0f;
        }

        const float* uA = uniform + (size_t)gb0 * (K_SAMP * D_IN);
        const float* uB = uniform + (size_t)gb1 * (K_SAMP * D_IN);

        float ua[8], ub[8];
        // load k=0 (tail guarded: keeps global reads in-bounds, junk lanes get 0.5)
#pragma unroll
        for (int i = 0; i < 3; i++) {
            float2 a = *(const float2*)&uA[2 * lane + 64 * i];
            float2 b = *(const float2*)&uB[2 * lane + 64 * i];
            ua[2 * i] = a.x; ua[2 * i + 1] = a.y;
            ub[2 * i] = b.x; ub[2 * i + 1] = b.y;
        }
        if (v3) {
            float2 a = *(const float2*)&uA[2 * lane + 192];
            float2 b = *(const float2*)&uB[2 * lane + 192];
            ua[6] = a.x; ua[7] = a.y; ub[6] = b.x; ub[7] = b.y;
        } else { ua[6] = 0.5f; ua[7] = 0.5f; ub[6] = 0.5f; ub[7] = 0.5f; }

#pragma unroll
        for (int k = 0; k < K_SAMP; k++) {
            float na[8], nb[8];
            if (k < K_SAMP - 1) {
                const float* pa = uA + (k + 1) * D_IN;
                const float* pb = uB + (k + 1) * D_IN;
#pragma unroll
                for (int i = 0; i < 3; i++) {
                    float2 a = *(const float2*)&pa[2 * lane + 64 * i];
                    float2 b = *(const float2*)&pb[2 * lane + 64 * i];
                    na[2 * i] = a.x; na[2 * i + 1] = a.y;
                    nb[2 * i] = b.x; nb[2 * i + 1] = b.y;
                }
                if (v3) {
                    float2 a = *(const float2*)&pa[2 * lane + 192];
                    float2 b = *(const float2*)&pb[2 * lane + 192];
                    na[6] = a.x; na[7] = a.y; nb[6] = b.x; nb[7] = b.y;
                } else { na[6] = 0.5f; na[7] = 0.5f; nb[6] = 0.5f; nb[7] = 0.5f; }
            }
            float wA[8], wB[8], sumA = 0.0f, sumB = 0.0f;
#pragma unroll
            for (int i = 0; i < 8; i++) {
                float u = fmaxf(ua[i], EPSF);
                float tl = -__logf(u);
                float xm = u - 1.0f;
                float tp = xm * fmaf(xm, fmaf(xm, -0.33333333f, 0.5f), -1.0f);
                float t = (u > 0.99f) ? tp : tl;
                float r = frcp(t);
                float w = EA[i] * r * r;
                wA[i] = w; sumA += w;

                float u2 = fmaxf(ub[i], EPSF);
                float tl2 = -__logf(u2);
                float xm2 = u2 - 1.0f;
                float tp2 = xm2 * fmaf(xm2, fmaf(xm2, -0.33333333f, 0.5f), -1.0f);
                float t2 = (u2 > 0.99f) ? tp2 : tl2;
                float r2 = frcp(t2);
                float w2v = EB[i] * r2 * r2;
                wB[i] = w2v; sumB += w2v;
            }
#pragma unroll
            for (int off = 16; off > 0; off >>= 1) {
                sumA += __shfl_xor_sync(0xffffffffu, sumA, off);
                sumB += __shfl_xor_sync(0xffffffffu, sumB, off);
            }
            float ia = frcp(sumA), ib = frcp(sumB);
#pragma unroll
            for (int i = 0; i < 8; i++) {
                sa[i] = fmaxf(sa[i], wA[i] * ia);
                sb[i] = fmaxf(sb[i], wB[i] * ib);
            }
            if (k < K_SAMP - 1) {
#pragma unroll
                for (int i = 0; i < 8; i++) { ua[i] = na[i]; ub[i] = nb[i]; }
            }
        }

        // samples out
#pragma unroll
        for (int i = 0; i < 4; i++) {
            if (i < 3 || v3) {
                int d = 2 * lane + 64 * i;
                *(float2*)&samples_out[(size_t)gb0 * 200 + d] = make_float2(sa[2 * i], sa[2 * i + 1]);
                *(float2*)&samples_out[(size_t)gb1 * 200 + d] = make_float2(sb[2 * i], sb[2 * i + 1]);
            }
        }
        // preds head
        float p0A = 0, p1A = 0, p0B = 0, p1B = 0;
#pragma unroll
        for (int i = 0; i < 4; i++) {
            if (i < 3 || v3) {
                int d = 2 * lane + 64 * i;
                float2 xa = *(const float2*)&x[(size_t)gb0 * 200 + d];
                float2 xb2 = *(const float2*)&x[(size_t)gb1 * 200 + d];
                float4 w4 = *(const float4*)&wo[d * 2];
                float xa0 = xa.x * sa[2 * i], xa1 = xa.y * sa[2 * i + 1];
                p0A += xa0 * w4.x + xa1 * w4.z;
                p1A += xa0 * w4.y + xa1 * w4.w;
                float xb0 = xb2.x * sb[2 * i], xb1 = xb2.y * sb[2 * i + 1];
                p0B += xb0 * w4.x + xb1 * w4.z;
                p1B += xb0 * w4.y + xb1 * w4.w;
            }
        }
#pragma unroll
        for (int off = 16; off > 0; off >>= 1) {
            p0A += __shfl_xor_sync(0xffffffffu, p0A, off);
            p1A += __shfl_xor_sync(0xffffffffu, p1A, off);
            p0B += __shfl_xor_sync(0xffffffffu, p0B, off);
            p1B += __shfl_xor_sync(0xffffffffu, p1B, off);
        }
        if (lane == 0) {
            float q0 = p0A + bo[0], q1 = p1A + bo[1];
            float mm = fmaxf(q0, q1);
            float e0 = __expf(q0 - mm), e1 = __expf(q1 - mm);
            float is = 1.0f / (e0 + e1);
            out[(size_t)gb0 * 2 + 0] = e0 * is;
            out[(size_t)gb0 * 2 + 1] = e1 * is;
            q0 = p0B + bo[0]; q1 = p1B + bo[1];
            mm = fmaxf(q0, q1);
            e0 = __expf(q0 - mm); e1 = __expf(q1 - mm);
            is = 1.0f / (e0 + e1);
            out[(size_t)gb1 * 2 + 0] = e0 * is;
            out[(size_t)gb1 * 2 + 1] = e1 * is;
        }
    }
}

extern "C" void kernel_launch(void* const* d_in, const int* in_sizes, int n_in,
                              void* d_out, int out_size) {
    const float* x  = (const float*)d_in[0];
    const float* un = (const float*)d_in[1];
    const float* w1 = (const float*)d_in[2];
    const float* b1 = (const float*)d_in[3];
    const float* w2 = (const float*)d_in[4];
    const float* b2 = (const float*)d_in[5];
    const float* wl = (const float*)d_in[6];
    const float* bl = (const float*)d_in[7];
    const float* wo = (const float*)d_in[8];
    const float* bo = (const float*)d_in[9];
    float* out = (float*)d_out;

    const int smem_bytes = SMEM_FLOATS * (int)sizeof(float);  // 112640
    static int configured = -1;
    cudaFuncSetAttribute(fused_kernel, cudaFuncAttributeMaxDynamicSharedMemorySize, smem_bytes);
    (void)configured;

    fused_kernel<<<B_ROWS / TM, 256, smem_bytes>>>(x, un, w1, b1, w2, b2, wl, bl, wo, bo, out);
}